// round 5
// baseline (speedup 1.0000x reference)
#include <cuda_runtime.h>
#include <cuda_bf16.h>

// FM_12060268167845: factorization machine forward.
//   d_in[0] idx  i32 [B,K], d_in[1] x f32 [B,K], d_in[2] b f32 [B,K],
//   d_in[3] w f32 [1M,1], d_in[4] V f32 [1M,128], d_in[5] bias f32 [1]
// out f32 [B] = sigmoid(bias + Xw + 0.5/sum(x) * sum_f((XV)^2 - X2V2))
//
// v4: warp-per-row, lane owns 4 factors (float4 -> warp-wide 512B burst).
// Software double-buffering (U=5, two register buffers): loads for the next
// batch are issued BEFORE consuming the current one, so every warp keeps
// >=5 LDG.128 outstanding at all times -> no DRAM idle gaps between the
// load and compute phases. 8 CTAs/SM retained (regs <= 64).

#define FM_B 8192
#define FM_K 200
#define FM_F 128
#define ROWS_PER_BLOCK 4
#define THREADS (ROWS_PER_BLOCK * 32)
#define U 5                        // batch size; FM_K = 40 batches

__device__ __forceinline__ void load_batch(float4 (&v)[U],
                                           const char* __restrict__ Vb,
                                           const unsigned* __restrict__ s_off,
                                           int k0, unsigned lane_off)
{
    #pragma unroll
    for (int u = 0; u < U; ++u) {
        unsigned off = s_off[k0 + u];
        v[u] = __ldcg((const float4*)(Vb + off + lane_off));
    }
}

__device__ __forceinline__ void consume_batch(const float4 (&v)[U],
                                              const float* __restrict__ s_x,
                                              int k0, float4& a1, float& a2s)
{
    #pragma unroll
    for (int u = 0; u < U; ++u) {
        float x  = s_x[k0 + u];
        float x2 = x * x;
        a1.x = fmaf(x, v[u].x, a1.x);
        a1.y = fmaf(x, v[u].y, a1.y);
        a1.z = fmaf(x, v[u].z, a1.z);
        a1.w = fmaf(x, v[u].w, a1.w);
        float n2 = fmaf(v[u].x, v[u].x,
                   fmaf(v[u].y, v[u].y,
                   fmaf(v[u].z, v[u].z, v[u].w * v[u].w)));
        a2s = fmaf(x2, n2, a2s);
    }
}

__global__ __launch_bounds__(THREADS, 8)
void fm_kernel(const int* __restrict__ idx,
               const float* __restrict__ x_vals,
               const float* __restrict__ b_vals,
               const float* __restrict__ w,
               const float* __restrict__ V,
               const float* __restrict__ bias,
               float* __restrict__ out)
{
    const int warp = threadIdx.x >> 5;
    const int lane = threadIdx.x & 31;
    const int b    = blockIdx.x * ROWS_PER_BLOCK + warp;

    __shared__ unsigned s_off[ROWS_PER_BLOCK][FM_K];
    __shared__ float    s_x[ROWS_PER_BLOCK][FM_K];

    // Stage byte offsets + x; fold in linear term and sum(x).
    float xw = 0.0f;
    float sx = 0.0f;
    const int base = b * FM_K;
    for (int k = lane; k < FM_K; k += 32) {
        int   id = idx[base + k];
        float xv = x_vals[base + k];
        s_off[warp][k] = (unsigned)id * (FM_F * 4u);   // id * 512 bytes
        s_x[warp][k]   = xv;
        sx += xv;
        xw = fmaf(b_vals[base + k], __ldg(&w[id]), xw);
    }
    __syncwarp();

    const char* __restrict__ Vb = (const char*)V;
    const unsigned lane_off = (unsigned)lane << 4;
    const unsigned* __restrict__ offp = s_off[warp];
    const float*    __restrict__ xp   = s_x[warp];

    float4 a1  = make_float4(0.f, 0.f, 0.f, 0.f);
    float  a2s = 0.0f;

    float4 v0[U], v1[U];
    load_batch(v0, Vb, offp, 0, lane_off);

    // Pair-pipelined mainloop: always >= U loads outstanding.
    for (int k0 = 0; k0 < FM_K - 2 * U; k0 += 2 * U) {
        load_batch(v1, Vb, offp, k0 + U, lane_off);
        consume_batch(v0, xp, k0, a1, a2s);
        load_batch(v0, Vb, offp, k0 + 2 * U, lane_off);
        consume_batch(v1, xp, k0 + U, a1, a2s);
    }
    // Epilogue: v0 holds batch @ FM_K-2U; one more load, two consumes.
    load_batch(v1, Vb, offp, FM_K - U, lane_off);
    consume_batch(v0, xp, FM_K - 2 * U, a1, a2s);
    consume_batch(v1, xp, FM_K - U, a1, a2s);

    float pq = fmaf(a1.x, a1.x,
               fmaf(a1.y, a1.y,
               fmaf(a1.z, a1.z, a1.w * a1.w))) - a2s;

    #pragma unroll
    for (int o = 16; o > 0; o >>= 1) {
        pq += __shfl_down_sync(0xffffffffu, pq, o);
        xw += __shfl_down_sync(0xffffffffu, xw, o);
        sx += __shfl_down_sync(0xffffffffu, sx, o);
    }

    if (lane == 0) {
        float p     = 0.5f * (1.0f / sx) * pq;
        float logit = bias[0] + xw + p;
        out[b] = 1.0f / (1.0f + __expf(-logit));
    }
}

extern "C" void kernel_launch(void* const* d_in, const int* in_sizes, int n_in,
                              void* d_out, int out_size)
{
    const int*   idx    = (const int*)d_in[0];
    const float* x_vals = (const float*)d_in[1];
    const float* b_vals = (const float*)d_in[2];
    const float* w      = (const float*)d_in[3];
    const float* V      = (const float*)d_in[4];
    const float* bias   = (const float*)d_in[5];
    float*       out    = (float*)d_out;
    (void)in_sizes; (void)n_in; (void)out_size;

    fm_kernel<<<FM_B / ROWS_PER_BLOCK, THREADS>>>(idx, x_vals, b_vals, w, V, bias, out);
}

// round 6
// speedup vs baseline: 1.0005x; 1.0005x over previous
#include <cuda_runtime.h>
#include <cuda_bf16.h>

// FM_12060268167845: factorization machine forward.
//   d_in[0] idx  i32 [B,K], d_in[1] x f32 [B,K], d_in[2] b f32 [B,K],
//   d_in[3] w f32 [1M,1], d_in[4] V f32 [1M,128], d_in[5] bias f32 [1]
// out f32 [B] = sigmoid(bias + Xw + 0.5/sum(x) * sum_f((XV)^2 - X2V2))
//
// v5: v3 mainloop (U=8 front-batched LDG.128, known 113.2us / 81.6% DRAM)
// with finer CTA granularity: 2 rows per 64-thread block, 16 CTAs/SM
// (same 1024 threads/SM, regfile-full at 64 regs). 4096 blocks -> smoother
// wave tail and less per-SM imbalance. Single-variable change vs v3.

#define FM_B 8192
#define FM_K 200
#define FM_F 128
#define ROWS_PER_BLOCK 2
#define THREADS (ROWS_PER_BLOCK * 32)
#define U 8                       // FM_K % U == 0

__global__ __launch_bounds__(THREADS, 16)
void fm_kernel(const int* __restrict__ idx,
               const float* __restrict__ x_vals,
               const float* __restrict__ b_vals,
               const float* __restrict__ w,
               const float* __restrict__ V,
               const float* __restrict__ bias,
               float* __restrict__ out)
{
    const int warp = threadIdx.x >> 5;
    const int lane = threadIdx.x & 31;
    const int b    = blockIdx.x * ROWS_PER_BLOCK + warp;

    __shared__ unsigned s_off[ROWS_PER_BLOCK][FM_K];
    __shared__ float    s_x[ROWS_PER_BLOCK][FM_K];

    // Stage byte offsets + x into shared; fold in linear term and sum(x).
    float xw = 0.0f;   // sum_k b_vals * w[idx]
    float sx = 0.0f;   // sum_k x_vals
    const int base = b * FM_K;
    for (int k = lane; k < FM_K; k += 32) {
        int   id = idx[base + k];
        float xv = x_vals[base + k];
        s_off[warp][k] = (unsigned)id * (FM_F * 4u);   // id * 512 bytes
        s_x[warp][k]   = xv;
        sx += xv;
        xw = fmaf(b_vals[base + k], __ldg(&w[id]), xw);
    }
    __syncwarp();

    const char* __restrict__ Vb = (const char*)V;
    const unsigned lane_off = (unsigned)lane << 4;     // lane * 16 bytes
    const unsigned* __restrict__ offp = s_off[warp];
    const float*    __restrict__ xp   = s_x[warp];

    float4 a1  = make_float4(0.f, 0.f, 0.f, 0.f);      // XV[4 factors]
    float  a2s = 0.0f;                                 // sum_f X2V2 slice

    for (int k0 = 0; k0 < FM_K; k0 += U) {
        float4 v[U];
        float  xr[U];
        // Front-batch U independent LDG.128s (warp-wide 512B row bursts).
        #pragma unroll
        for (int u = 0; u < U; ++u) {
            unsigned off = offp[k0 + u];
            xr[u] = xp[k0 + u];
            v[u]  = __ldg((const float4*)(Vb + off + lane_off));
        }
        #pragma unroll
        for (int u = 0; u < U; ++u) {
            float x  = xr[u];
            float x2 = x * x;
            a1.x = fmaf(x, v[u].x, a1.x);
            a1.y = fmaf(x, v[u].y, a1.y);
            a1.z = fmaf(x, v[u].z, a1.z);
            a1.w = fmaf(x, v[u].w, a1.w);
            float n2 = fmaf(v[u].x, v[u].x,
                       fmaf(v[u].y, v[u].y,
                       fmaf(v[u].z, v[u].z, v[u].w * v[u].w)));
            a2s = fmaf(x2, n2, a2s);
        }
    }

    // Per-lane interaction contribution over its 4 factors.
    float pq = fmaf(a1.x, a1.x,
               fmaf(a1.y, a1.y,
               fmaf(a1.z, a1.z, a1.w * a1.w))) - a2s;

    // Warp reduction of (pq, xw, sx).
    #pragma unroll
    for (int o = 16; o > 0; o >>= 1) {
        pq += __shfl_down_sync(0xffffffffu, pq, o);
        xw += __shfl_down_sync(0xffffffffu, xw, o);
        sx += __shfl_down_sync(0xffffffffu, sx, o);
    }

    if (lane == 0) {
        float p     = 0.5f * (1.0f / sx) * pq;
        float logit = bias[0] + xw + p;
        out[b] = 1.0f / (1.0f + __expf(-logit));
    }
}

extern "C" void kernel_launch(void* const* d_in, const int* in_sizes, int n_in,
                              void* d_out, int out_size)
{
    const int*   idx    = (const int*)d_in[0];
    const float* x_vals = (const float*)d_in[1];
    const float* b_vals = (const float*)d_in[2];
    const float* w      = (const float*)d_in[3];
    const float* V      = (const float*)d_in[4];
    const float* bias   = (const float*)d_in[5];
    float*       out    = (float*)d_out;
    (void)in_sizes; (void)n_in; (void)out_size;

    fm_kernel<<<FM_B / ROWS_PER_BLOCK, THREADS>>>(idx, x_vals, b_vals, w, V, bias, out);
}

// round 7
// speedup vs baseline: 1.0147x; 1.0142x over previous
#include <cuda_runtime.h>
#include <cuda_bf16.h>

// FM_12060268167845: factorization machine forward.
//   d_in[0] idx  i32 [B,K], d_in[1] x f32 [B,K], d_in[2] b f32 [B,K],
//   d_in[3] w f32 [1M,1], d_in[4] V f32 [1M,128], d_in[5] bias f32 [1]
// out f32 [B] = sigmoid(bias + Xw + 0.5/sum(x) * sum_f((XV)^2 - X2V2))
//
// v6: v3 core (warp-per-row, lane owns 4 factors -> warp-wide 512B LDG.128
// burst, U=8 front-batched loads) with the xr[] register buffer removed:
// x is read from shared inside the consume loop (LDS latency hidden by the
// FMA chain). Register target drops 64 -> 56, fitting 9 CTAs/SM
// (+12.5% warps at identical per-warp MLP) to smooth the DRAM queue.

#define FM_B 8192
#define FM_K 200
#define FM_F 128
#define ROWS_PER_BLOCK 4
#define THREADS (ROWS_PER_BLOCK * 32)
#define U 8                       // FM_K % U == 0

__global__ __launch_bounds__(THREADS, 9)
void fm_kernel(const int* __restrict__ idx,
               const float* __restrict__ x_vals,
               const float* __restrict__ b_vals,
               const float* __restrict__ w,
               const float* __restrict__ V,
               const float* __restrict__ bias,
               float* __restrict__ out)
{
    const int warp = threadIdx.x >> 5;
    const int lane = threadIdx.x & 31;
    const int b    = blockIdx.x * ROWS_PER_BLOCK + warp;

    __shared__ unsigned s_off[ROWS_PER_BLOCK][FM_K];
    __shared__ float    s_x[ROWS_PER_BLOCK][FM_K];

    // Stage byte offsets + x into shared; fold in linear term and sum(x).
    float xw = 0.0f;   // sum_k b_vals * w[idx]
    float sx = 0.0f;   // sum_k x_vals
    const int base = b * FM_K;
    for (int k = lane; k < FM_K; k += 32) {
        int   id = idx[base + k];
        float xv = x_vals[base + k];
        s_off[warp][k] = (unsigned)id * (FM_F * 4u);   // id * 512 bytes
        s_x[warp][k]   = xv;
        sx += xv;
        xw = fmaf(b_vals[base + k], __ldg(&w[id]), xw);
    }
    __syncwarp();

    const char* __restrict__ Vb = (const char*)V;
    const unsigned lane_off = (unsigned)lane << 4;     // lane * 16 bytes
    const unsigned* __restrict__ offp = s_off[warp];
    const float*    __restrict__ xp   = s_x[warp];

    float4 a1  = make_float4(0.f, 0.f, 0.f, 0.f);      // XV[4 factors]
    float  a2s = 0.0f;                                 // sum_f X2V2 slice

    for (int k0 = 0; k0 < FM_K; k0 += U) {
        float4 v[U];
        // Front-batch U independent LDG.128s (warp-wide 512B row bursts).
        #pragma unroll
        for (int u = 0; u < U; ++u) {
            v[u] = __ldg((const float4*)(Vb + offp[k0 + u] + lane_off));
        }
        // Consume: x comes straight from shared (latency hidden by FMAs).
        #pragma unroll
        for (int u = 0; u < U; ++u) {
            float x  = xp[k0 + u];
            float x2 = x * x;
            a1.x = fmaf(x, v[u].x, a1.x);
            a1.y = fmaf(x, v[u].y, a1.y);
            a1.z = fmaf(x, v[u].z, a1.z);
            a1.w = fmaf(x, v[u].w, a1.w);
            float n2 = fmaf(v[u].x, v[u].x,
                       fmaf(v[u].y, v[u].y,
                       fmaf(v[u].z, v[u].z, v[u].w * v[u].w)));
            a2s = fmaf(x2, n2, a2s);
        }
    }

    // Per-lane interaction contribution over its 4 factors.
    float pq = fmaf(a1.x, a1.x,
               fmaf(a1.y, a1.y,
               fmaf(a1.z, a1.z, a1.w * a1.w))) - a2s;

    // Warp reduction of (pq, xw, sx).
    #pragma unroll
    for (int o = 16; o > 0; o >>= 1) {
        pq += __shfl_down_sync(0xffffffffu, pq, o);
        xw += __shfl_down_sync(0xffffffffu, xw, o);
        sx += __shfl_down_sync(0xffffffffu, sx, o);
    }

    if (lane == 0) {
        float p     = 0.5f * (1.0f / sx) * pq;
        float logit = bias[0] + xw + p;
        out[b] = 1.0f / (1.0f + __expf(-logit));
    }
}

extern "C" void kernel_launch(void* const* d_in, const int* in_sizes, int n_in,
                              void* d_out, int out_size)
{
    const int*   idx    = (const int*)d_in[0];
    const float* x_vals = (const float*)d_in[1];
    const float* b_vals = (const float*)d_in[2];
    const float* w      = (const float*)d_in[3];
    const float* V      = (const float*)d_in[4];
    const float* bias   = (const float*)d_in[5];
    float*       out    = (float*)d_out;
    (void)in_sizes; (void)n_in; (void)out_size;

    fm_kernel<<<FM_B / ROWS_PER_BLOCK, THREADS>>>(idx, x_vals, b_vals, w, V, bias, out);
}